// round 14
// baseline (speedup 1.0000x reference)
#include <cuda_runtime.h>

#define NBINS 5
#define NT    256
#define UN2   8                 /* fused pass unroll: 8 x float4 per thread */
#define UN    4                 /* apply unroll */
#define GRID2 592               /* 148 SMs x 4 blocks -- all resident (launch_bounds) */
#define GRIDA 2048              /* apply grid */
#define TILE2 (NT * UN2)        /* 2048 float4 = 32KB */
#define TILE  (NT * UN)         /* 1024 float4 = 16KB */

// ---------------- device scratch (no allocation allowed) ----------------
__device__ float g_pmin[GRID2];
__device__ float g_pmax[GRID2];
__device__ uint4 g_ps[GRID2];               // per-block (s1,s2,s3,s4)
__device__ volatile unsigned int g_bar;     // grid barrier (self-resetting)
__device__ unsigned int g_tk;               // last-block ticket (self-resetting)
// table layout (36 floats):
//  [0..7]   (slopeA_i = slope_i*ct, base_i) for the 4 index(d) segments
//  [8..31]  6 x float4: (thSlope, thInt, veSlope, veInt) keyed by clamp(floor(index)+1,0,5)
//  [32] At = ct/width   [33] c0 = -dmin/width - 0.5   [34] stct = st*ct   [35] st
__device__ float g_tbl[36];

// ---------------- fused kernel: minmax (fwd) -> grid barrier -> hist (own-chunk reverse) ----
__device__ __forceinline__ void hist4(float4 v, float A, float B,
                                      unsigned int& s1, unsigned int& s2,
                                      unsigned int& s3, unsigned int& s4) {
    float q0 = fmaf(v.x, A, B);
    float q1 = fmaf(v.y, A, B);
    float q2 = fmaf(v.z, A, B);
    float q3 = fmaf(v.w, A, B);
    s1 += (q0 >= 1.0f) + (q1 >= 1.0f) + (q2 >= 1.0f) + (q3 >= 1.0f);
    s2 += (q0 >= 2.0f) + (q1 >= 2.0f) + (q2 >= 2.0f) + (q3 >= 2.0f);
    s3 += (q0 >= 3.0f) + (q1 >= 3.0f) + (q2 >= 3.0f) + (q3 >= 3.0f);
    s4 += (q0 >= 4.0f) + (q1 >= 4.0f) + (q2 >= 4.0f) + (q3 >= 4.0f);
}

__global__ __launch_bounds__(NT, 4)
void k_mmh(const float4* __restrict__ x, int n4,
           const float* __restrict__ xs, int n, int ntiles,
           const float* __restrict__ params,
           const float* __restrict__ ct_p,
           const float* __restrict__ st_p) {
    __shared__ float smn[NT / 32], smx[NT / 32];
    __shared__ float sAB[4];                 // A, B, dmin, width (broadcast)
    __shared__ unsigned int s_last;
    int w = threadIdx.x >> 5;
    int gtid = blockIdx.x * NT + threadIdx.x;

    // ---------- phase A: min/max, forward ----------
    float mn =  3.402823466e38f;
    float mx = -3.402823466e38f;
    int nt_b = 0;                            // tiles owned by this block
    for (int g = blockIdx.x; g < ntiles; g += GRID2) {
        int base = g * TILE2 + threadIdx.x;
        #pragma unroll
        for (int k = 0; k < UN2; k++) {
            float4 v = x[base + k * NT];
            mn = fminf(mn, fminf(fminf(v.x, v.y), fminf(v.z, v.w)));
            mx = fmaxf(mx, fmaxf(fmaxf(v.x, v.y), fmaxf(v.z, v.w)));
        }
        nt_b++;
    }
    for (int j = ntiles * TILE2 + gtid; j < n4; j += GRID2 * NT) {
        float4 v = x[j];
        mn = fminf(mn, fminf(fminf(v.x, v.y), fminf(v.z, v.w)));
        mx = fmaxf(mx, fmaxf(fmaxf(v.x, v.y), fmaxf(v.z, v.w)));
    }
    for (int j = (n4 << 2) + gtid; j < n; j += GRID2 * NT) {
        float v = xs[j];
        mn = fminf(mn, v); mx = fmaxf(mx, v);
    }
    #pragma unroll
    for (int o = 16; o > 0; o >>= 1) {
        mn = fminf(mn, __shfl_xor_sync(0xffffffffu, mn, o));
        mx = fmaxf(mx, __shfl_xor_sync(0xffffffffu, mx, o));
    }
    if ((threadIdx.x & 31) == 0) { smn[w] = mn; smx[w] = mx; }
    __syncthreads();

    // ---------- grid barrier (all 592 blocks resident by launch_bounds) ----------
    if (threadIdx.x == 0) {
        float bmn = smn[0], bmx = smx[0];
        #pragma unroll
        for (int k = 1; k < NT / 32; k++) { bmn = fminf(bmn, smn[k]); bmx = fmaxf(bmx, smx[k]); }
        g_pmin[blockIdx.x] = bmn;
        g_pmax[blockIdx.x] = bmx;
        __threadfence();
        atomicAdd((unsigned int*)&g_bar, 1u);
        while (g_bar < GRID2) __nanosleep(64);
    }
    __syncthreads();
    __threadfence();

    // ---------- every block reduces partials (identical result, no 2nd barrier) ----------
    {
        float rmn =  3.402823466e38f;
        float rmx = -3.402823466e38f;
        for (int i = threadIdx.x; i < GRID2; i += NT) {
            rmn = fminf(rmn, g_pmin[i]);
            rmx = fmaxf(rmx, g_pmax[i]);
        }
        #pragma unroll
        for (int o = 16; o > 0; o >>= 1) {
            rmn = fminf(rmn, __shfl_xor_sync(0xffffffffu, rmn, o));
            rmx = fmaxf(rmx, __shfl_xor_sync(0xffffffffu, rmx, o));
        }
        if ((threadIdx.x & 31) == 0) { smn[w] = rmn; smx[w] = rmx; }
        __syncthreads();
        if (threadIdx.x == 0) {
            #pragma unroll
            for (int k = 1; k < NT / 32; k++) { rmn = fminf(rmn, smn[k]); rmx = fmaxf(rmx, smx[k]); }
            float ct = ct_p[0];
            float a = ct * rmn, b = ct * rmx;       // monotone map, handles ct<0
            float dmn = fminf(a, b) - 0.1f;
            float dmx = fmaxf(a, b) + 0.1f;
            float wd = (dmx - dmn) / (float)NBINS;
            float invw = 1.0f / wd;
            sAB[0] = ct * invw;
            sAB[1] = -dmn * invw;
            sAB[2] = dmn;
            sAB[3] = wd;
        }
        __syncthreads();
    }
    const float A = sAB[0], B = sAB[1];

    // ---------- phase B: histogram, OWN tiles in REVERSE (L1/L2 hot) ----------
    unsigned int s1 = 0, s2 = 0, s3 = 0, s4 = 0;
    for (int i = nt_b - 1; i >= 0; i--) {
        int g = blockIdx.x + i * GRID2;
        int base = g * TILE2 + threadIdx.x;
        #pragma unroll
        for (int k = 0; k < UN2; k++)
            hist4(x[base + k * NT], A, B, s1, s2, s3, s4);
    }
    for (int j = ntiles * TILE2 + gtid; j < n4; j += GRID2 * NT)
        hist4(x[j], A, B, s1, s2, s3, s4);
    for (int j = (n4 << 2) + gtid; j < n; j += GRID2 * NT) {
        float q = fmaf(xs[j], A, B);
        s1 += (q >= 1.0f); s2 += (q >= 2.0f); s3 += (q >= 3.0f); s4 += (q >= 4.0f);
    }
    s1 = __reduce_add_sync(0xffffffffu, s1);
    s2 = __reduce_add_sync(0xffffffffu, s2);
    s3 = __reduce_add_sync(0xffffffffu, s3);
    s4 = __reduce_add_sync(0xffffffffu, s4);
    __shared__ unsigned int sc[4];
    if (threadIdx.x < 4) sc[threadIdx.x] = 0u;
    __syncthreads();
    if ((threadIdx.x & 31) == 0) {
        atomicAdd(&sc[0], s1); atomicAdd(&sc[1], s2);
        atomicAdd(&sc[2], s3); atomicAdd(&sc[3], s4);
    }
    __syncthreads();
    if (threadIdx.x == 0) {
        g_ps[blockIdx.x] = make_uint4(sc[0], sc[1], sc[2], sc[3]);
        __threadfence();
        unsigned int o = atomicAdd(&g_tk, 1u);
        s_last = (o == GRID2 - 1) ? 1u : 0u;
    }
    __syncthreads();
    if (!s_last) return;

    // ---------- last block: reduce hist partials + build tables ----------
    __threadfence();
    __shared__ float s_in[12];   // [0..9]=params, [10]=ct, [11]=st
    if (threadIdx.x < 10) s_in[threadIdx.x] = params[threadIdx.x];
    else if (threadIdx.x == 10) s_in[10] = ct_p[0];
    else if (threadIdx.x == 11) s_in[11] = st_p[0];

    unsigned int a1 = 0, a2 = 0, a3 = 0, a4 = 0;
    for (int i = threadIdx.x; i < GRID2; i += NT) {
        uint4 p = g_ps[i];
        a1 += p.x; a2 += p.y; a3 += p.z; a4 += p.w;
    }
    a1 = __reduce_add_sync(0xffffffffu, a1);
    a2 = __reduce_add_sync(0xffffffffu, a2);
    a3 = __reduce_add_sync(0xffffffffu, a3);
    a4 = __reduce_add_sync(0xffffffffu, a4);
    __shared__ unsigned int sr[4][NT / 32];
    if ((threadIdx.x & 31) == 0) { sr[0][w] = a1; sr[1][w] = a2; sr[2][w] = a3; sr[3][w] = a4; }
    __syncthreads();
    if (threadIdx.x != 0) return;
    #pragma unroll
    for (int k = 1; k < NT / 32; k++) { a1 += sr[0][k]; a2 += sr[1][k]; a3 += sr[2][k]; a4 += sr[3][k]; }

    const float dmin = sAB[2], wdt = sAB[3];
    const float ct = s_in[10], st = s_in[11];

    unsigned long long cnt[NBINS];
    cnt[0] = (unsigned long long)n - a1;
    cnt[1] = a1 - a2; cnt[2] = a2 - a3; cnt[3] = a3 - a4; cnt[4] = a4;

    // emulate fp32 +=1.0 accumulation: saturates exactly at 2^24
    float cf[NBINS];
    #pragma unroll
    for (int i = 0; i < NBINS; i++) {
        unsigned long long c = cnt[i];
        if (c > 16777216ull) c = 16777216ull;
        cf[i] = (float)c;
    }
    float s = cf[0] + cf[1] + cf[2] + cf[3] + cf[4];       // left-to-right fp32
    float accum[NBINS];
    float run = 0.0f;
    #pragma unroll
    for (int i = 0; i < NBINS; i++) {
        float prob = cf[i] / s;
        run += prob;
        accum[i] = run * (float)NBINS;
    }
    float edges[NBINS + 1], grid[NBINS];
    #pragma unroll
    for (int i = 0; i <= NBINS; i++) edges[i] = dmin + wdt * (float)i;
    #pragma unroll
    for (int i = 0; i < NBINS; i++) grid[i] = 0.5f * (edges[i + 1] + edges[i]);

    // per-segment (slope*ct, base) for index(x) = interp1d(grid, accum, x*ct)
    #pragma unroll
    for (int i = 0; i < NBINS - 1; i++) {
        float den = grid[i + 1] - grid[i];
        if (den == 0.0f) den = 1.0f;
        float slope = (accum[i + 1] - accum[i]) / den;
        g_tbl[2 * i]     = slope * ct;
        g_tbl[2 * i + 1] = accum[i] - slope * grid[i];
    }
    // frame = interp1d(accum, grid, arange(P))
    float frame[NBINS];
    #pragma unroll
    for (int q = 0; q < NBINS; q++) {
        float xq = (float)q;
        int ss = 0;
        #pragma unroll
        for (int j = 0; j < NBINS; j++) ss += (accum[j] < xq);
        int idx = min(max(ss - 1, 0), NBINS - 2);
        float den = accum[idx + 1] - accum[idx];
        if (den == 0.0f) den = 1.0f;
        frame[q] = grid[idx] + (grid[idx + 1] - grid[idx]) / den * (xq - accum[idx]);
    }
    float thp[NBINS], vep[NBINS];
    #pragma unroll
    for (int q = 0; q < NBINS; q++) {
        thp[q] = frame[q] + 0.001f * s_in[q];
        vep[q] = frame[q] + 0.001f * s_in[NBINS + q];
    }
    // 6 segments of (slope, intercept) in `index`, key = clamp(floor(index)+1, 0, 5)
    #pragma unroll
    for (int k = 0; k < 6; k++) {
        float tS, tI, vS, vI;
        if (k == 0)      { tS = 0.0f; tI = thp[0]; vS = 0.0f; vI = vep[0]; }
        else if (k == 5) { tS = 0.0f; tI = thp[4]; vS = 0.0f; vI = vep[4]; }
        else {
            int bi = k - 1;
            tS = thp[bi + 1] - thp[bi]; tI = thp[bi] - tS * (float)bi;
            vS = vep[bi + 1] - vep[bi]; vI = vep[bi] - vS * (float)bi;
        }
        g_tbl[8 + 4 * k + 0] = tS;
        g_tbl[8 + 4 * k + 1] = tI;
        g_tbl[8 + 4 * k + 2] = vS;
        g_tbl[8 + 4 * k + 3] = vI;
    }
    float invw = 1.0f / wdt;
    g_tbl[32] = ct * invw;
    g_tbl[33] = -dmin * invw - 0.5f;
    g_tbl[34] = st * ct;
    g_tbl[35] = st;
    // reset sync state for next graph replay (all blocks past barrier by now)
    g_bar = 0u;
    __threadfence();
    atomicExch(&g_tk, 0u);
}

// ---------------- kernel 2: elementwise apply ----------------
// Stage-1 table lives in registers (ts/ti[0..3]); selection by t-thresholds is
// bit-identical to idx = clamp(floor(t),0,3) gathering. Stage-2 stays LDS.128.
__device__ __forceinline__ float apply_one(float xv, const float4* cf,
                                           float s0x, float s0y, float s1x, float s1y,
                                           float s2x, float s2y, float s3x, float s3y,
                                           float At, float c0, float stct, float st) {
    float t = fmaf(xv, At, c0);
    float sxa = (t >= 1.0f) ? s1x : s0x;
    float sya = (t >= 1.0f) ? s1y : s0y;
    float sxb = (t >= 3.0f) ? s3x : s2x;
    float syb = (t >= 3.0f) ? s3y : s2y;
    bool hi = (t >= 2.0f);
    float sx = hi ? sxb : sxa;
    float sy = hi ? syb : sya;
    float index = fmaf(xv, sx, sy);
    int k = min(max(__float2int_rd(index) + 1, 0), 5);
    float4 c = cf[k];
    float th = fmaf(index, c.x, c.y);
    float ve = fmaf(index, c.z, c.w);
    float sn, cs;
    __sincosf(th, &sn, &cs);
    return fmaf(xv, stct * fmaf(ve, sn, 1.0f), st * (ve * cs));
}

#define APPLY1(xv) apply_one((xv), cf, s0x, s0y, s1x, s1y, s2x, s2y, s3x, s3y, At, c0, stct, st)

__global__ void k_apply(const float4* __restrict__ x, float4* __restrict__ o, int n4,
                        const float* __restrict__ xs, float* __restrict__ os, int n, int ntiles) {
    __shared__ __align__(16) float tbl[36];
    if (threadIdx.x < 36) tbl[threadIdx.x] = g_tbl[threadIdx.x];
    __syncthreads();
    const float4* cf = (const float4*)(tbl + 8);    // 6 quads (stage 2)
    // stage-1 pairs -> registers
    const float s0x = tbl[0], s0y = tbl[1];
    const float s1x = tbl[2], s1y = tbl[3];
    const float s2x = tbl[4], s2y = tbl[5];
    const float s3x = tbl[6], s3y = tbl[7];
    const float At = tbl[32], c0 = tbl[33], stct = tbl[34], st = tbl[35];
    for (int g = blockIdx.x; g < ntiles; g += GRIDA) {
        int base = g * TILE + threadIdx.x;
        float4 v0 = __ldcs(&x[base]);
        float4 v1 = __ldcs(&x[base + NT]);
        float4 v2 = __ldcs(&x[base + 2 * NT]);
        float4 v3 = __ldcs(&x[base + 3 * NT]);
        float4 r0, r1, r2, r3;
        r0.x = APPLY1(v0.x); r0.y = APPLY1(v0.y); r0.z = APPLY1(v0.z); r0.w = APPLY1(v0.w);
        r1.x = APPLY1(v1.x); r1.y = APPLY1(v1.y); r1.z = APPLY1(v1.z); r1.w = APPLY1(v1.w);
        r2.x = APPLY1(v2.x); r2.y = APPLY1(v2.y); r2.z = APPLY1(v2.z); r2.w = APPLY1(v2.w);
        r3.x = APPLY1(v3.x); r3.y = APPLY1(v3.y); r3.z = APPLY1(v3.z); r3.w = APPLY1(v3.w);
        __stwt(&o[base], r0);                       // write-through: no L2 pollution
        __stwt(&o[base + NT], r1);
        __stwt(&o[base + 2 * NT], r2);
        __stwt(&o[base + 3 * NT], r3);
    }
    int gtid = blockIdx.x * NT + threadIdx.x;
    for (int j = ntiles * TILE + gtid; j < n4; j += GRIDA * NT) {
        float4 v = __ldcs(&x[j]);
        float4 r;
        r.x = APPLY1(v.x); r.y = APPLY1(v.y); r.z = APPLY1(v.z); r.w = APPLY1(v.w);
        __stwt(&o[j], r);
    }
    for (int j = (n4 << 2) + gtid; j < n; j += GRIDA * NT)
        __stwt(&os[j], APPLY1(xs[j]));
}

// ---------------- launch ----------------
extern "C" void kernel_launch(void* const* d_in, const int* in_sizes, int n_in,
                              void* d_out, int out_size) {
    const float* data   = (const float*)d_in[0];
    const float* params = (const float*)d_in[1];
    const float* ct     = (const float*)d_in[2];
    const float* st     = (const float*)d_in[3];
    float* out = (float*)d_out;
    int n       = in_sizes[0];
    int n4      = n >> 2;
    int ntiles2 = n4 / TILE2;
    int ntiles  = n4 / TILE;

    k_mmh<<<GRID2, NT>>>((const float4*)data, n4, data, n, ntiles2, params, ct, st);
    k_apply<<<GRIDA, NT>>>((const float4*)data, (float4*)out, n4, data, out, n, ntiles);
}

// round 16
// speedup vs baseline: 1.0599x; 1.0599x over previous
#include <cuda_runtime.h>

#define NBINS 5
#define NT    256
#define UN2   8                 /* tile = 8 x float4 per thread = 32KB */
#define GRID2 592               /* 148 SMs x 4 blocks -- all resident (launch_bounds) */
#define TILE2 (NT * UN2)

// ---------------- device scratch (no allocation allowed) ----------------
__device__ float g_pmin[GRID2];
__device__ float g_pmax[GRID2];
__device__ uint4 g_ps[GRID2];               // per-block (s1,s2,s3,s4)
__device__ volatile unsigned int g_bar1;    // grid barrier A->B (self-resetting)
__device__ volatile unsigned int g_bar2;    // grid barrier B->C (self-resetting)
__device__ unsigned int g_tk;               // final ticket (self-resetting)

__device__ __forceinline__ void hist4(float4 v, float A, float B,
                                      unsigned int& s1, unsigned int& s2,
                                      unsigned int& s3, unsigned int& s4) {
    float q0 = fmaf(v.x, A, B);
    float q1 = fmaf(v.y, A, B);
    float q2 = fmaf(v.z, A, B);
    float q3 = fmaf(v.w, A, B);
    s1 += (q0 >= 1.0f) + (q1 >= 1.0f) + (q2 >= 1.0f) + (q3 >= 1.0f);
    s2 += (q0 >= 2.0f) + (q1 >= 2.0f) + (q2 >= 2.0f) + (q3 >= 2.0f);
    s3 += (q0 >= 3.0f) + (q1 >= 3.0f) + (q2 >= 3.0f) + (q3 >= 3.0f);
    s4 += (q0 >= 4.0f) + (q1 >= 4.0f) + (q2 >= 4.0f) + (q3 >= 4.0f);
}

// stage-1 in registers; selection bit-identical to idx = clamp(floor(t),0,3) gather
__device__ __forceinline__ float apply_one(float xv, const float4* cf,
                                           float s0x, float s0y, float s1x, float s1y,
                                           float s2x, float s2y, float s3x, float s3y,
                                           float At, float c0, float stct, float st) {
    float t = fmaf(xv, At, c0);
    float sxa = (t >= 1.0f) ? s1x : s0x;
    float sya = (t >= 1.0f) ? s1y : s0y;
    float sxb = (t >= 3.0f) ? s3x : s2x;
    float syb = (t >= 3.0f) ? s3y : s2y;
    bool hi = (t >= 2.0f);
    float sx = hi ? sxb : sxa;
    float sy = hi ? syb : sya;
    float index = fmaf(xv, sx, sy);
    int k = min(max(__float2int_rd(index) + 1, 0), 5);
    float4 c = cf[k];
    float th = fmaf(index, c.x, c.y);
    float ve = fmaf(index, c.z, c.w);
    float sn, cs;
    __sincosf(th, &sn, &cs);
    return fmaf(xv, stct * fmaf(ve, sn, 1.0f), st * (ve * cs));
}

#define APPLY1(xv) apply_one((xv), cf, s0x, s0y, s1x, s1y, s2x, s2y, s3x, s3y, At, c0, stct, st)

// ============ single persistent kernel: minmax -> hist -> apply ============
__global__ __launch_bounds__(NT, 4)
void k_fused(const float4* __restrict__ x, float4* __restrict__ o, int n4,
             const float* __restrict__ xs, float* __restrict__ os, int n, int ntiles,
             const float* __restrict__ params,
             const float* __restrict__ ct_p,
             const float* __restrict__ st_p) {
    __shared__ float smn[NT / 32], smx[NT / 32];
    __shared__ float sAB[4];                  // A, B, dmin, width
    __shared__ unsigned int sc[4];
    __shared__ unsigned int sr[4][NT / 32];
    __shared__ float s_in[12];                // params(10), ct, st
    __shared__ __align__(16) float tbl[36];   // stage1(8) | cf 6xfloat4(24) | At,c0,stct,st
    int w = threadIdx.x >> 5;
    int gtid = blockIdx.x * NT + threadIdx.x;

    // prefetch scalar inputs early (overlaps phase A)
    if (threadIdx.x < 10) s_in[threadIdx.x] = params[threadIdx.x];
    else if (threadIdx.x == 10) s_in[10] = ct_p[0];
    else if (threadIdx.x == 11) s_in[11] = st_p[0];

    // ---------- phase A: min/max, own tiles forward ----------
    float mn =  3.402823466e38f;
    float mx = -3.402823466e38f;
    int nt_b = 0;
    for (int g = blockIdx.x; g < ntiles; g += GRID2) {
        int base = g * TILE2 + threadIdx.x;
        #pragma unroll
        for (int k = 0; k < UN2; k++) {
            float4 v = x[base + k * NT];
            mn = fminf(mn, fminf(fminf(v.x, v.y), fminf(v.z, v.w)));
            mx = fmaxf(mx, fmaxf(fmaxf(v.x, v.y), fmaxf(v.z, v.w)));
        }
        nt_b++;
    }
    for (int j = ntiles * TILE2 + gtid; j < n4; j += GRID2 * NT) {
        float4 v = x[j];
        mn = fminf(mn, fminf(fminf(v.x, v.y), fminf(v.z, v.w)));
        mx = fmaxf(mx, fmaxf(fmaxf(v.x, v.y), fmaxf(v.z, v.w)));
    }
    for (int j = (n4 << 2) + gtid; j < n; j += GRID2 * NT) {
        float v = xs[j];
        mn = fminf(mn, v); mx = fmaxf(mx, v);
    }
    #pragma unroll
    for (int oo = 16; oo > 0; oo >>= 1) {
        mn = fminf(mn, __shfl_xor_sync(0xffffffffu, mn, oo));
        mx = fmaxf(mx, __shfl_xor_sync(0xffffffffu, mx, oo));
    }
    if ((threadIdx.x & 31) == 0) { smn[w] = mn; smx[w] = mx; }
    __syncthreads();

    // ---------- grid barrier 1 ----------
    if (threadIdx.x == 0) {
        float bmn = smn[0], bmx = smx[0];
        #pragma unroll
        for (int k = 1; k < NT / 32; k++) { bmn = fminf(bmn, smn[k]); bmx = fmaxf(bmx, smx[k]); }
        g_pmin[blockIdx.x] = bmn;
        g_pmax[blockIdx.x] = bmx;
        __threadfence();
        atomicAdd((unsigned int*)&g_bar1, 1u);
        while (g_bar1 < GRID2) __nanosleep(64);
    }
    __syncthreads();
    __threadfence();

    // ---------- every block reduces minmax partials (identical result) ----------
    {
        float rmn =  3.402823466e38f;
        float rmx = -3.402823466e38f;
        for (int i = threadIdx.x; i < GRID2; i += NT) {
            rmn = fminf(rmn, g_pmin[i]);
            rmx = fmaxf(rmx, g_pmax[i]);
        }
        #pragma unroll
        for (int oo = 16; oo > 0; oo >>= 1) {
            rmn = fminf(rmn, __shfl_xor_sync(0xffffffffu, rmn, oo));
            rmx = fmaxf(rmx, __shfl_xor_sync(0xffffffffu, rmx, oo));
        }
        if ((threadIdx.x & 31) == 0) { smn[w] = rmn; smx[w] = rmx; }
        __syncthreads();
        if (threadIdx.x == 0) {
            #pragma unroll
            for (int k = 1; k < NT / 32; k++) { rmn = fminf(rmn, smn[k]); rmx = fmaxf(rmx, smx[k]); }
            float ct = s_in[10];
            float a = ct * rmn, b = ct * rmx;     // monotone map, handles ct<0
            float dmn = fminf(a, b) - 0.1f;
            float dmx = fmaxf(a, b) + 0.1f;
            float wd = (dmx - dmn) / (float)NBINS;
            float invw = 1.0f / wd;
            sAB[0] = ct * invw;
            sAB[1] = -dmn * invw;
            sAB[2] = dmn;
            sAB[3] = wd;
        }
        __syncthreads();
    }
    const float A = sAB[0], B = sAB[1];

    // ---------- phase B: histogram, own tiles in REVERSE (L1/L2 hot) ----------
    unsigned int s1 = 0, s2 = 0, s3 = 0, s4 = 0;
    for (int i = nt_b - 1; i >= 0; i--) {
        int g = blockIdx.x + i * GRID2;
        int base = g * TILE2 + threadIdx.x;
        #pragma unroll
        for (int k = 0; k < UN2; k++)
            hist4(x[base + k * NT], A, B, s1, s2, s3, s4);
    }
    for (int j = ntiles * TILE2 + gtid; j < n4; j += GRID2 * NT)
        hist4(x[j], A, B, s1, s2, s3, s4);
    for (int j = (n4 << 2) + gtid; j < n; j += GRID2 * NT) {
        float q = fmaf(xs[j], A, B);
        s1 += (q >= 1.0f); s2 += (q >= 2.0f); s3 += (q >= 3.0f); s4 += (q >= 4.0f);
    }
    s1 = __reduce_add_sync(0xffffffffu, s1);
    s2 = __reduce_add_sync(0xffffffffu, s2);
    s3 = __reduce_add_sync(0xffffffffu, s3);
    s4 = __reduce_add_sync(0xffffffffu, s4);
    if (threadIdx.x < 4) sc[threadIdx.x] = 0u;
    __syncthreads();
    if ((threadIdx.x & 31) == 0) {
        atomicAdd(&sc[0], s1); atomicAdd(&sc[1], s2);
        atomicAdd(&sc[2], s3); atomicAdd(&sc[3], s4);
    }
    __syncthreads();

    // ---------- grid barrier 2 ----------
    if (threadIdx.x == 0) {
        g_ps[blockIdx.x] = make_uint4(sc[0], sc[1], sc[2], sc[3]);
        __threadfence();
        atomicAdd((unsigned int*)&g_bar2, 1u);
        while (g_bar2 < GRID2) __nanosleep(64);
    }
    __syncthreads();
    __threadfence();

    // ---------- every block: reduce hist partials + build table (identical) ----------
    {
        unsigned int a1 = 0, a2 = 0, a3 = 0, a4 = 0;
        for (int i = threadIdx.x; i < GRID2; i += NT) {
            uint4 p = g_ps[i];
            a1 += p.x; a2 += p.y; a3 += p.z; a4 += p.w;
        }
        a1 = __reduce_add_sync(0xffffffffu, a1);
        a2 = __reduce_add_sync(0xffffffffu, a2);
        a3 = __reduce_add_sync(0xffffffffu, a3);
        a4 = __reduce_add_sync(0xffffffffu, a4);
        if ((threadIdx.x & 31) == 0) { sr[0][w] = a1; sr[1][w] = a2; sr[2][w] = a3; sr[3][w] = a4; }
        __syncthreads();
        if (threadIdx.x == 0) {
            #pragma unroll
            for (int k = 1; k < NT / 32; k++) { a1 += sr[0][k]; a2 += sr[1][k]; a3 += sr[2][k]; a4 += sr[3][k]; }
            const float dmin = sAB[2], wdt = sAB[3];
            const float ct = s_in[10], st = s_in[11];

            unsigned long long cnt[NBINS];
            cnt[0] = (unsigned long long)n - a1;
            cnt[1] = a1 - a2; cnt[2] = a2 - a3; cnt[3] = a3 - a4; cnt[4] = a4;

            // emulate fp32 +=1.0 accumulation: saturates exactly at 2^24
            float cf5[NBINS];
            #pragma unroll
            for (int i = 0; i < NBINS; i++) {
                unsigned long long c = cnt[i];
                if (c > 16777216ull) c = 16777216ull;
                cf5[i] = (float)c;
            }
            float s = cf5[0] + cf5[1] + cf5[2] + cf5[3] + cf5[4];   // left-to-right fp32
            float accum[NBINS];
            float run = 0.0f;
            #pragma unroll
            for (int i = 0; i < NBINS; i++) {
                float prob = cf5[i] / s;
                run += prob;
                accum[i] = run * (float)NBINS;
            }
            float edges[NBINS + 1], grid[NBINS];
            #pragma unroll
            for (int i = 0; i <= NBINS; i++) edges[i] = dmin + wdt * (float)i;
            #pragma unroll
            for (int i = 0; i < NBINS; i++) grid[i] = 0.5f * (edges[i + 1] + edges[i]);

            #pragma unroll
            for (int i = 0; i < NBINS - 1; i++) {
                float den = grid[i + 1] - grid[i];
                if (den == 0.0f) den = 1.0f;
                float slope = (accum[i + 1] - accum[i]) / den;
                tbl[2 * i]     = slope * ct;
                tbl[2 * i + 1] = accum[i] - slope * grid[i];
            }
            float frame[NBINS];
            #pragma unroll
            for (int q = 0; q < NBINS; q++) {
                float xq = (float)q;
                int ss = 0;
                #pragma unroll
                for (int j = 0; j < NBINS; j++) ss += (accum[j] < xq);
                int idx = min(max(ss - 1, 0), NBINS - 2);
                float den = accum[idx + 1] - accum[idx];
                if (den == 0.0f) den = 1.0f;
                frame[q] = grid[idx] + (grid[idx + 1] - grid[idx]) / den * (xq - accum[idx]);
            }
            float thp[NBINS], vep[NBINS];
            #pragma unroll
            for (int q = 0; q < NBINS; q++) {
                thp[q] = frame[q] + 0.001f * s_in[q];
                vep[q] = frame[q] + 0.001f * s_in[NBINS + q];
            }
            #pragma unroll
            for (int k = 0; k < 6; k++) {
                float tS, tI, vS, vI;
                if (k == 0)      { tS = 0.0f; tI = thp[0]; vS = 0.0f; vI = vep[0]; }
                else if (k == 5) { tS = 0.0f; tI = thp[4]; vS = 0.0f; vI = vep[4]; }
                else {
                    int bi = k - 1;
                    tS = thp[bi + 1] - thp[bi]; tI = thp[bi] - tS * (float)bi;
                    vS = vep[bi + 1] - vep[bi]; vI = vep[bi] - vS * (float)bi;
                }
                tbl[8 + 4 * k + 0] = tS;
                tbl[8 + 4 * k + 1] = tI;
                tbl[8 + 4 * k + 2] = vS;
                tbl[8 + 4 * k + 3] = vI;
            }
            float invw = 1.0f / wdt;
            tbl[32] = A;                       // == ct/width
            tbl[33] = B - 0.5f;                // == -dmin/width - 0.5
            tbl[34] = st * ct;
            tbl[35] = st;
            (void)invw;
        }
        __syncthreads();
    }

    // ---------- phase C: apply, own tiles FORWARD (LIFO of phase B -> warm) ----------
    const float4* cf = (const float4*)(tbl + 8);
    const float s0x = tbl[0], s0y = tbl[1];
    const float s1x = tbl[2], s1y = tbl[3];
    const float s2x = tbl[4], s2y = tbl[5];
    const float s3x = tbl[6], s3y = tbl[7];
    const float At = tbl[32], c0 = tbl[33], stct = tbl[34], st = tbl[35];
    for (int i = 0; i < nt_b; i++) {
        int g = blockIdx.x + i * GRID2;
        int base = g * TILE2 + threadIdx.x;
        #pragma unroll
        for (int h = 0; h < 2; h++) {          // two half-tiles of 4 float4
            int b2 = base + h * 4 * NT;
            float4 v0 = __ldcs(&x[b2]);
            float4 v1 = __ldcs(&x[b2 + NT]);
            float4 v2 = __ldcs(&x[b2 + 2 * NT]);
            float4 v3 = __ldcs(&x[b2 + 3 * NT]);
            float4 r0, r1, r2, r3;
            r0.x = APPLY1(v0.x); r0.y = APPLY1(v0.y); r0.z = APPLY1(v0.z); r0.w = APPLY1(v0.w);
            r1.x = APPLY1(v1.x); r1.y = APPLY1(v1.y); r1.z = APPLY1(v1.z); r1.w = APPLY1(v1.w);
            r2.x = APPLY1(v2.x); r2.y = APPLY1(v2.y); r2.z = APPLY1(v2.z); r2.w = APPLY1(v2.w);
            r3.x = APPLY1(v3.x); r3.y = APPLY1(v3.y); r3.z = APPLY1(v3.z); r3.w = APPLY1(v3.w);
            __stcs(&o[b2], r0);
            __stcs(&o[b2 + NT], r1);
            __stcs(&o[b2 + 2 * NT], r2);
            __stcs(&o[b2 + 3 * NT], r3);
        }
    }
    for (int j = ntiles * TILE2 + gtid; j < n4; j += GRID2 * NT) {
        float4 v = __ldcs(&x[j]);
        float4 r;
        r.x = APPLY1(v.x); r.y = APPLY1(v.y); r.z = APPLY1(v.z); r.w = APPLY1(v.w);
        __stcs(&o[j], r);
    }
    for (int j = (n4 << 2) + gtid; j < n; j += GRID2 * NT)
        os[j] = APPLY1(xs[j]);

    // ---------- final ticket: last block resets sync state for next replay ----------
    __syncthreads();
    if (threadIdx.x == 0) {
        unsigned int t = atomicAdd(&g_tk, 1u);
        if (t == GRID2 - 1) {
            g_bar1 = 0u;
            g_bar2 = 0u;
            __threadfence();
            atomicExch(&g_tk, 0u);
        }
    }
}

// ---------------- launch ----------------
extern "C" void kernel_launch(void* const* d_in, const int* in_sizes, int n_in,
                              void* d_out, int out_size) {
    const float* data   = (const float*)d_in[0];
    const float* params = (const float*)d_in[1];
    const float* ct     = (const float*)d_in[2];
    const float* st     = (const float*)d_in[3];
    float* out = (float*)d_out;
    int n       = in_sizes[0];
    int n4      = n >> 2;
    int ntiles2 = n4 / TILE2;

    k_fused<<<GRID2, NT>>>((const float4*)data, (float4*)out, n4, data, out, n,
                           ntiles2, params, ct, st);
}